// round 14
// baseline (speedup 1.0000x reference)
#include <cuda_runtime.h>
#include <cuda_fp16.h>
#include <cstdint>

// Problem constants
#define S_   1024
#define B_   8
#define D_   1024
#define H_   16
#define HD_  64
#define T_   (B_ * S_)
#define D3_  (3 * D_)

// Scratch
__device__ __half g_qkvh[(size_t)T_ * 3 * D_];
__device__ __half g_attnh[(size_t)T_ * D_];
__device__ float  g_attnout[(size_t)T_ * D_];
__device__ float  g_linv[B_ * H_ * S_];
__device__ __half g_xh[(size_t)T_ * D_];
__device__ __half g_wih[(size_t)D3_ * D_];
__device__ __half g_woh[(size_t)D_ * D_];

__device__ __forceinline__ unsigned su32(const void* p) {
    return (unsigned)__cvta_generic_to_shared(p);
}
__device__ __forceinline__ void cpa16(unsigned dst, const void* src) {
    asm volatile("cp.async.cg.shared.global [%0], [%1], 16;" :: "r"(dst), "l"(src));
}
#define CP_COMMIT() asm volatile("cp.async.commit_group;")
#define CP_WAIT0()  asm volatile("cp.async.wait_group 0;")
#define CP_WAIT1()  asm volatile("cp.async.wait_group 1;")

__device__ __forceinline__ unsigned pkh2(float a, float b) {
    __half2 h = __floats2half2_rn(a, b);
    return *(unsigned*)&h;
}

// fp16 m16n8k16
__device__ __forceinline__ void mma16h(float* d, const unsigned* a, const unsigned* b) {
    asm volatile(
        "mma.sync.aligned.m16n8k16.row.col.f32.f16.f16.f32 "
        "{%0,%1,%2,%3},{%4,%5,%6,%7},{%8,%9},{%0,%1,%2,%3};"
        : "+f"(d[0]), "+f"(d[1]), "+f"(d[2]), "+f"(d[3])
        : "r"(a[0]), "r"(a[1]), "r"(a[2]), "r"(a[3]), "r"(b[0]), "r"(b[1]));
}
__device__ __forceinline__ void ldm4(unsigned* r, unsigned addr) {
    asm volatile("ldmatrix.sync.aligned.m8n8.x4.shared.b16 {%0,%1,%2,%3}, [%4];"
        : "=r"(r[0]), "=r"(r[1]), "=r"(r[2]), "=r"(r[3]) : "r"(addr));
}
__device__ __forceinline__ void ldm4t(unsigned* r, unsigned addr) {
    asm volatile("ldmatrix.sync.aligned.m8n8.x4.trans.shared.b16 {%0,%1,%2,%3}, [%4];"
        : "=r"(r[0]), "=r"(r[1]), "=r"(r[2]), "=r"(r[3]) : "r"(addr));
}

#define FST 72
#define GSLAB (128 * FST)
#define OUTPROJ_BLOCKS ((D_ / 128) * (T_ / 128))   // 512

// ---------------------------------------------------------------------------
// fp32 -> fp16 conversion: three segments in one launch
// ---------------------------------------------------------------------------
__global__ void __launch_bounds__(256) to_half3_kernel(
    const float* __restrict__ s0, __half* __restrict__ d0, int n0,
    const float* __restrict__ s1, __half* __restrict__ d1, int n1,
    const float* __restrict__ s2, __half* __restrict__ d2, int n2)
{
    int i = blockIdx.x * blockDim.x + threadIdx.x;
    const float* src;
    __half* dst;
    if (i < n0) { src = s0; dst = d0; }
    else if (i < n0 + n1) { i -= n0; src = s1; dst = d1; }
    else if (i < n0 + n1 + n2) { i -= n0 + n1; src = s2; dst = d2; }
    else return;
    float4 v = ((const float4*)src)[i];
    ((__half2*)dst)[2 * i]     = __floats2half2_rn(v.x, v.y);
    ((__half2*)dst)[2 * i + 1] = __floats2half2_rn(v.z, v.w);
}

// ---------------------------------------------------------------------------
// GEMM tile body (R11/R13 config): 128x128 tile, 4 warps (2x2), warp 64x64,
// BK=64, 3-stage cp.async, prefetch distance 2, one barrier/iter.
// ---------------------------------------------------------------------------
template<bool HALF_OUT>
__device__ __forceinline__ void gemm_tile_body(
    const __half* __restrict__ A, const __half* __restrict__ Bm,
    const float* __restrict__ bias, void* __restrict__ Cv,
    int N, int K, int m0, int n0)
{
    extern __shared__ __half smh[];

    const int tid  = threadIdx.x;
    const int lane = tid & 31;
    const int wid  = tid >> 5;
    const int wm   = wid >> 1;
    const int wn   = wid & 1;
    const int gid = lane >> 2;
    const int tig = lane & 3;

    const int aRow = lane & 15;
    const int aCol = (lane >> 4) << 3;
    const int bRow = ((lane >> 4) << 3) + (lane & 7);
    const int bCol = ((lane >> 3) & 1) << 3;

    auto load_slab = [&](int slab, int st) {
        const int k0 = slab * 64;
        const __half* Asrc = A  + (size_t)m0 * K + k0;
        const __half* Bsrc = Bm + (size_t)n0 * K + k0;
        __half* Ab = smh + st * (2 * GSLAB);
        __half* Bb = Ab + GSLAB;
#pragma unroll
        for (int l = 0; l < 8; l++) {
            int lin = tid + l * 128;
            int r = lin >> 3;
            int u = lin & 7;
            cpa16(su32(Ab + r * FST + u * 8), Asrc + (size_t)r * K + u * 8);
            cpa16(su32(Bb + r * FST + u * 8), Bsrc + (size_t)r * K + u * 8);
        }
        CP_COMMIT();
    };

    float acc[4][8][4];
#pragma unroll
    for (int i = 0; i < 4; i++)
#pragma unroll
        for (int j = 0; j < 8; j++)
#pragma unroll
            for (int r = 0; r < 4; r++) acc[i][j][r] = 0.f;

    load_slab(0, 0); load_slab(1, 1);

    const int NIT = K / 64;
    for (int i = 0; i < NIT; i++) {
        const int st = i % 3;
        if (i + 1 < NIT) { CP_WAIT1(); } else { CP_WAIT0(); }
        __syncthreads();
        if (i + 2 < NIT) load_slab(i + 2, (i + 2) % 3);

        const __half* Ac = smh + st * (2 * GSLAB);
        const __half* Bc = Ac + GSLAB;

#pragma unroll
        for (int ks = 0; ks < 4; ks++) {
            unsigned af[4][4], bf[4][4];
#pragma unroll
            for (int mi = 0; mi < 4; mi++)
                ldm4(af[mi], su32(Ac + (wm * 64 + mi * 16 + aRow) * FST + ks * 16 + aCol));
#pragma unroll
            for (int nj = 0; nj < 4; nj++)
                ldm4(bf[nj], su32(Bc + (wn * 64 + nj * 16 + bRow) * FST + ks * 16 + bCol));
#pragma unroll
            for (int mi = 0; mi < 4; mi++)
#pragma unroll
                for (int ni = 0; ni < 8; ni++)
                    mma16h(acc[mi][ni], af[mi], &bf[ni >> 1][(ni & 1) * 2]);
        }
    }

#pragma unroll
    for (int mi = 0; mi < 4; mi++) {
        int m = m0 + wm * 64 + mi * 16 + gid;
#pragma unroll
        for (int ni = 0; ni < 8; ni++) {
            int n = n0 + wn * 64 + ni * 8 + 2 * tig;
            float bx = bias[n], by = bias[n + 1];
            if (HALF_OUT) {
                __half* C = (__half*)Cv;
                *(__half2*)(C + (size_t)m * N + n) =
                    __floats2half2_rn(acc[mi][ni][0] + bx, acc[mi][ni][1] + by);
                *(__half2*)(C + (size_t)(m + 8) * N + n) =
                    __floats2half2_rn(acc[mi][ni][2] + bx, acc[mi][ni][3] + by);
            } else {
                float* C = (float*)Cv;
                *(float2*)(C + (size_t)m * N + n) =
                    make_float2(acc[mi][ni][0] + bx, acc[mi][ni][1] + by);
                *(float2*)(C + (size_t)(m + 8) * N + n) =
                    make_float2(acc[mi][ni][2] + bx, acc[mi][ni][3] + by);
            }
        }
    }
}

// ---------------------------------------------------------------------------
// QKV GEMM (standalone)
// ---------------------------------------------------------------------------
__global__ void __launch_bounds__(128) gemm_qkv_kernel(
    const __half* __restrict__ A, const __half* __restrict__ Bm,
    const float* __restrict__ bias, __half* __restrict__ C,
    int M, int N, int K)
{
    gemm_tile_body<true>(A, Bm, bias, C, N, K,
                         blockIdx.y * 128, blockIdx.x * 128);
}

// ---------------------------------------------------------------------------
// Weights tile body (R13 config incl. hoisted bias)
// ---------------------------------------------------------------------------
__device__ __forceinline__ void weights_tile_body(
    float atd, float* __restrict__ wout, int qt, int b, int kt)
{
    extern __shared__ __half smh[];
    __half* Qb = smh;
    __half* Kb = smh + 2 * 64 * FST;
    float*  lsb = (float*)(smh + 4 * 64 * FST);

    const int tid  = threadIdx.x;
    const int lane = tid & 31;
    const int wid  = tid >> 5;
    const float scale = 0.125f;
    const int gid = lane >> 2;
    const int tig = lane & 3;

    const int aRow = lane & 15;
    const int aCol = (lane >> 4) << 3;
    const int bRow = ((lane >> 4) << 3) + (lane & 7);
    const int bCol = ((lane >> 3) & 1) << 3;

    auto issue = [&](int h, int bf) {
        const __half* qb = g_qkvh + (size_t)(b * S_ + qt * 64) * D3_ + h * HD_;
        const __half* kb = g_qkvh + (size_t)(b * S_ + kt * 64) * D3_ + D_ + h * HD_;
        __half* Qd = Qb + bf * 64 * FST;
        __half* Kd = Kb + bf * 64 * FST;
#pragma unroll
        for (int l = 0; l < 8; l++) {
            int lin = tid + l * 128;
            int r = lin >> 3;
            int u = lin & 7;
            if (r < 64)
                cpa16(su32(Qd + r * FST + u * 8), qb + (size_t)r * D3_ + u * 8);
            else
                cpa16(su32(Kd + (r - 64) * FST + u * 8), kb + (size_t)(r - 64) * D3_ + u * 8);
        }
        CP_COMMIT();
    };

    issue(0, 0);
    {
        int si0 = (b * H_ + 0) * S_ + qt * 64;
        if (tid < 64) lsb[tid] = g_linv[si0 + tid];
    }

    float biasv[4][2][4];
#pragma unroll
    for (int mi = 0; mi < 4; mi++) {
        float qg0 = (float)(qt * 64 + mi * 16 + gid);
        float qg1 = qg0 + 8.f;
#pragma unroll
        for (int ni = 0; ni < 2; ni++) {
            float c0 = (float)(kt * 64 + wid * 16 + ni * 8 + 2 * tig);
            biasv[mi][ni][0] = atd * fabsf(qg0 - c0);
            biasv[mi][ni][1] = atd * fabsf(qg0 - c0 - 1.f);
            biasv[mi][ni][2] = atd * fabsf(qg1 - c0);
            biasv[mi][ni][3] = atd * fabsf(qg1 - c0 - 1.f);
        }
    }

    float wsum[4][2][4];
#pragma unroll
    for (int mi = 0; mi < 4; mi++)
#pragma unroll
        for (int ni = 0; ni < 2; ni++)
#pragma unroll
            for (int r = 0; r < 4; r++) wsum[mi][ni][r] = 0.f;

    for (int h = 0; h < H_; h++) {
        const int bf = h & 1;
        CP_WAIT0();
        __syncthreads();
        if (h < 15) {
            issue(h + 1, bf ^ 1);
            int si0 = (b * H_ + h + 1) * S_ + qt * 64;
            if (tid < 64) lsb[(bf ^ 1) * 64 + tid] = g_linv[si0 + tid];
        }
        const __half* Qc = Qb + bf * 64 * FST;
        const __half* Kc = Kb + bf * 64 * FST;
        const float* ls = lsb + bf * 64;

        float acc[4][2][4];
#pragma unroll
        for (int mi = 0; mi < 4; mi++)
#pragma unroll
            for (int ni = 0; ni < 2; ni++)
#pragma unroll
                for (int r = 0; r < 4; r++) acc[mi][ni][r] = 0.f;

#pragma unroll
        for (int ks = 0; ks < 4; ks++) {
            unsigned bfr[4];
            ldm4(bfr, su32(Kc + (wid * 16 + bRow) * FST + ks * 16 + bCol));
#pragma unroll
            for (int mi = 0; mi < 4; mi++) {
                unsigned af[4];
                ldm4(af, su32(Qc + (mi * 16 + aRow) * FST + ks * 16 + aCol));
                mma16h(acc[mi][0], af, &bfr[0]);
                mma16h(acc[mi][1], af, &bfr[2]);
            }
        }

#pragma unroll
        for (int mi = 0; mi < 4; mi++) {
            float l0v = ls[mi * 16 + gid];
            float l1v = ls[mi * 16 + gid + 8];
#pragma unroll
            for (int ni = 0; ni < 2; ni++) {
                wsum[mi][ni][0] += __expf(fmaf(acc[mi][ni][0], scale, -biasv[mi][ni][0])) * l0v;
                wsum[mi][ni][1] += __expf(fmaf(acc[mi][ni][1], scale, -biasv[mi][ni][1])) * l0v;
                wsum[mi][ni][2] += __expf(fmaf(acc[mi][ni][2], scale, -biasv[mi][ni][2])) * l1v;
                wsum[mi][ni][3] += __expf(fmaf(acc[mi][ni][3], scale, -biasv[mi][ni][3])) * l1v;
            }
        }
    }

    const float inv_h = 1.0f / (float)H_;
#pragma unroll
    for (int mi = 0; mi < 4; mi++) {
        int r0 = qt * 64 + mi * 16 + gid;
#pragma unroll
        for (int ni = 0; ni < 2; ni++) {
            int c = kt * 64 + wid * 16 + ni * 8 + 2 * tig;
            float2 o0 = make_float2(wsum[mi][ni][0] * inv_h, wsum[mi][ni][1] * inv_h);
            float2 o1 = make_float2(wsum[mi][ni][2] * inv_h, wsum[mi][ni][3] * inv_h);
            *(float2*)(wout + (size_t)(b * S_ + r0) * S_ + c) = o0;
            *(float2*)(wout + (size_t)(b * S_ + r0 + 8) * S_ + c) = o1;
        }
    }
}

// ---------------------------------------------------------------------------
// Fused: out-projection GEMM blocks [0, 512) + weights blocks [512, 2560).
// Both are independent post-flash; co-residency mixes tensor- and MUFU-bound
// work on each SM.
// ---------------------------------------------------------------------------
__global__ void __launch_bounds__(128) fused_wo_kernel(
    const float* __restrict__ td_ptr, float* __restrict__ wout,
    const float* __restrict__ out_b)
{
    const int bx = blockIdx.x;
    if (bx < OUTPROJ_BLOCKS) {
        // out-proj: C[T_, D_] = attnh @ woh^T + out_b
        int n0 = (bx & 7) * 128;          // D_/128 = 8
        int m0 = (bx >> 3) * 128;
        gemm_tile_body<false>(g_attnh, g_woh, out_b, g_attnout, D_, D_, m0, n0);
    } else {
        int idx = bx - OUTPROJ_BLOCKS;
        int qt = idx & 15;
        int b  = (idx >> 4) & 7;
        int kt = idx >> 7;
        weights_tile_body(fabsf(*td_ptr), wout, qt, b, kt);
    }
}

// ---------------------------------------------------------------------------
// Flash attention, fp16 MMA (unchanged — known good).
// ---------------------------------------------------------------------------
__global__ void __launch_bounds__(256) flash_kernel(const float* __restrict__ td_ptr)
{
    extern __shared__ __half smh[];
    __half* Qs  = smh;
    __half* Ksb = smh + 128 * FST;
    __half* Vsb = Ksb + 2 * 64 * FST;

    const int tid  = threadIdx.x;
    const int lane = tid & 31;
    const int w    = tid >> 5;
    const int gid  = lane >> 2;
    const int tig  = lane & 3;
    const int bh = blockIdx.x;
    const int qt = blockIdx.y;
    const int b  = bh >> 4;
    const int h  = bh & 15;
    const float atd = fabsf(*td_ptr);
    const float scale = 0.125f;

    const int aRow = lane & 15;
    const int aCol = (lane >> 4) << 3;
    const int bRow = ((lane >> 4) << 3) + (lane & 7);
    const int bCol = ((lane >> 3) & 1) << 3;

    {
        const __half* qb = g_qkvh + (size_t)(b * S_ + qt * 128) * D3_ + h * HD_;
#pragma unroll
        for (int l = 0; l < 4; l++) {
            int lin = tid + l * 256;
            int r = lin >> 3;
            int u = lin & 7;
            cpa16(su32(Qs + r * FST + u * 8), qb + (size_t)r * D3_ + u * 8);
        }
    }
    auto issueKV = [&](int kt, int bf) {
        const __half* kb = g_qkvh + (size_t)(b * S_ + kt * 64) * D3_ + D_ + h * HD_;
        const __half* vb = kb + D_;
        __half* Kd = Ksb + bf * 64 * FST;
        __half* Vd = Vsb + bf * 64 * FST;
#pragma unroll
        for (int l = 0; l < 4; l++) {
            int lin = tid + l * 256;
            int r = lin >> 3;
            int u = lin & 7;
            if (r < 64)
                cpa16(su32(Kd + r * FST + u * 8), kb + (size_t)r * D3_ + u * 8);
            else
                cpa16(su32(Vd + (r - 64) * FST + u * 8), vb + (size_t)(r - 64) * D3_ + u * 8);
        }
        CP_COMMIT();
    };

    issueKV(0, 0);
    CP_WAIT0();
    __syncthreads();

    unsigned qf[4][4];
#pragma unroll
    for (int s = 0; s < 4; s++)
        ldm4(qf[s], su32(Qs + (w * 16 + aRow) * FST + s * 16 + aCol));

    float oacc[8][4];
#pragma unroll
    for (int n = 0; n < 8; n++)
#pragma unroll
        for (int r = 0; r < 4; r++) oacc[n][r] = 0.f;
    float ls0 = 0.f, ls1 = 0.f;

    const float qg0f = (float)(qt * 128 + w * 16 + gid);
    const float qg1f = qg0f + 8.f;

    for (int kt = 0; kt < 16; kt++) {
        CP_WAIT0();
        __syncthreads();
        if (kt < 15) issueKV(kt + 1, (kt + 1) & 1);
        const __half* Kc = Ksb + (kt & 1) * 64 * FST;
        const __half* Vc = Vsb + (kt & 1) * 64 * FST;

        float sacc[8][4];
#pragma unroll
        for (int n = 0; n < 8; n++)
#pragma unroll
            for (int r = 0; r < 4; r++) sacc[n][r] = 0.f;
#pragma unroll
        for (int s = 0; s < 4; s++) {
#pragma unroll
            for (int nj = 0; nj < 4; nj++) {
                unsigned kb[4];
                ldm4(kb, su32(Kc + (nj * 16 + bRow) * FST + s * 16 + bCol));
                mma16h(sacc[2 * nj],     qf[s], &kb[0]);
                mma16h(sacc[2 * nj + 1], qf[s], &kb[2]);
            }
        }

        unsigned pa[4][4];
#pragma unroll
        for (int nb = 0; nb < 8; nb++) {
            float c0 = (float)(kt * 64 + nb * 8 + 2 * tig);
            float p00 = __expf(sacc[nb][0] * scale - atd * fabsf(qg0f - c0));
            float p01 = __expf(sacc[nb][1] * scale - atd * fabsf(qg0f - c0 - 1.f));
            float p10 = __expf(sacc[nb][2] * scale - atd * fabsf(qg1f - c0));
            float p11 = __expf(sacc[nb][3] * scale - atd * fabsf(qg1f - c0 - 1.f));
            ls0 += p00 + p01; ls1 += p10 + p11;
            int j = nb >> 1;
            if ((nb & 1) == 0) {
                pa[j][0] = pkh2(p00, p01);
                pa[j][1] = pkh2(p10, p11);
            } else {
                pa[j][2] = pkh2(p00, p01);
                pa[j][3] = pkh2(p10, p11);
            }
        }

#pragma unroll
        for (int j = 0; j < 4; j++) {
#pragma unroll
            for (int nd = 0; nd < 4; nd++) {
                unsigned vb[4];
                ldm4t(vb, su32(Vc + (j * 16 + aRow) * FST + nd * 16 + aCol));
                mma16h(oacc[2 * nd],     pa[j], &vb[0]);
                mma16h(oacc[2 * nd + 1], pa[j], &vb[2]);
            }
        }
    }

#pragma unroll
    for (int o = 1; o <= 2; o <<= 1) {
        ls0 += __shfl_xor_sync(0xffffffffu, ls0, o);
        ls1 += __shfl_xor_sync(0xffffffffu, ls1, o);
    }
    float inv0 = 1.f / ls0, inv1 = 1.f / ls1;
    int t0 = b * S_ + qt * 128 + w * 16 + gid;
#pragma unroll
    for (int nb = 0; nb < 8; nb++) {
        int c = h * HD_ + nb * 8 + 2 * tig;
        *(__half2*)&g_attnh[(size_t)t0 * D_ + c] =
            __floats2half2_rn(oacc[nb][0] * inv0, oacc[nb][1] * inv0);
        *(__half2*)&g_attnh[(size_t)(t0 + 8) * D_ + c] =
            __floats2half2_rn(oacc[nb][2] * inv1, oacc[nb][3] * inv1);
    }
    if (tig == 0) {
        int si = (b * H_ + h) * S_ + qt * 128 + w * 16 + gid;
        g_linv[si] = inv0;
        g_linv[si + 8] = inv1;
    }
}

// ---------------------------------------------------------------------------
// Residual + LayerNorm
// ---------------------------------------------------------------------------
__global__ void __launch_bounds__(256) ln_kernel(
    const float* __restrict__ x, const float* __restrict__ lnw,
    const float* __restrict__ lnb, float* __restrict__ out)
{
    const int row = blockIdx.x;
    const int tid = threadIdx.x;
    const float* xr = x + (size_t)row * D_;
    const float* ar = g_attnout + (size_t)row * D_;

    float4 xv = *(const float4*)(xr + tid * 4);
    float4 av = *(const float4*)(ar + tid * 4);
    float y[4];
    y[0] = xv.x + av.x; y[1] = xv.y + av.y;
    y[2] = xv.z + av.z; y[3] = xv.w + av.w;

    float s  = y[0] + y[1] + y[2] + y[3];
    float sq = y[0]*y[0] + y[1]*y[1] + y[2]*y[2] + y[3]*y[3];
#pragma unroll
    for (int o = 16; o >= 1; o >>= 1) {
        s  += __shfl_xor_sync(0xffffffffu, s,  o);
        sq += __shfl_xor_sync(0xffffffffu, sq, o);
    }
    __shared__ float red[16];
    const int wid = tid >> 5;
    if ((tid & 31) == 0) { red[wid] = s; red[8 + wid] = sq; }
    __syncthreads();
    float st = 0.f, sqt = 0.f;
#pragma unroll
    for (int w = 0; w < 8; w++) { st += red[w]; sqt += red[8 + w]; }
    float mu = st * (1.0f / D_);
    float var = sqt * (1.0f / D_) - mu * mu;
    float rstd = rsqrtf(var + 1e-5f);

    float4 wv = *(const float4*)(lnw + tid * 4);
    float4 bv = *(const float4*)(lnb + tid * 4);
    float4 o4;
    o4.x = (y[0] - mu) * rstd * wv.x + bv.x;
    o4.y = (y[1] - mu) * rstd * wv.y + bv.y;
    o4.z = (y[2] - mu) * rstd * wv.z + bv.z;
    o4.w = (y[3] - mu) * rstd * wv.w + bv.w;
    *(float4*)(out + (size_t)row * D_ + tid * 4) = o4;
}

// ---------------------------------------------------------------------------
extern "C" void kernel_launch(void* const* d_in, const int* in_sizes, int n_in,
                              void* d_out, int out_size)
{
    (void)in_sizes; (void)n_in; (void)out_size;
    const float* x     = (const float*)d_in[0];
    const float* td    = (const float*)d_in[1];
    const float* in_w  = (const float*)d_in[2];
    const float* in_b  = (const float*)d_in[3];
    const float* out_w = (const float*)d_in[4];
    const float* out_b = (const float*)d_in[5];
    const float* lnw   = (const float*)d_in[6];
    const float* lnb   = (const float*)d_in[7];
    float* out  = (float*)d_out;
    float* wout = out + (size_t)T_ * D_;

    __half *xh_p, *wih_p, *woh_p, *qkvh_p;
    cudaGetSymbolAddress((void**)&xh_p, g_xh);
    cudaGetSymbolAddress((void**)&wih_p, g_wih);
    cudaGetSymbolAddress((void**)&woh_p, g_woh);
    cudaGetSymbolAddress((void**)&qkvh_p, g_qkvh);

    const int gsmem = 3 * 2 * GSLAB * 2;                     // 110592 B
    const int fsmem = (128 * FST + 4 * 64 * FST) * 2;        // 55296 B
    cudaFuncSetAttribute(gemm_qkv_kernel,
                         cudaFuncAttributeMaxDynamicSharedMemorySize, gsmem);
    cudaFuncSetAttribute(fused_wo_kernel,
                         cudaFuncAttributeMaxDynamicSharedMemorySize, gsmem);
    cudaFuncSetAttribute(flash_kernel,
                         cudaFuncAttributeMaxDynamicSharedMemorySize, fsmem);

    // 0. Convert GEMM inputs to fp16 (single launch, three segments)
    {
        int n0 = (T_ * D_) / 4;
        int n1 = (D3_ * D_) / 4;
        int n2 = (D_ * D_) / 4;
        int nt = n0 + n1 + n2;
        to_half3_kernel<<<(nt + 255) / 256, 256>>>(
            x, xh_p, n0, in_w, wih_p, n1, out_w, woh_p, n2);
    }

    // 1. QKV projection -> fp16 qkv
    gemm_qkv_kernel<<<dim3(3 * D_ / 128, T_ / 128), 128, gsmem>>>(
        xh_p, wih_p, in_b, qkvh_p, T_, 3 * D_, D_);

    // 2. Flash attention (fp16 MMA) -> g_attnh, g_linv
    flash_kernel<<<dim3(B_ * H_, S_ / 128), 256, fsmem>>>(td);

    // 3. Fused: out-projection GEMM + head-mean weights (independent, overlap)
    fused_wo_kernel<<<OUTPROJ_BLOCKS + S_ / 64 * B_ * (S_ / 64), 128, gsmem>>>(
        td, wout, out_b);

    // 4. Residual + LayerNorm
    ln_kernel<<<T_, 256>>>(x, lnw, lnb, out);
}

// round 15
// speedup vs baseline: 1.0992x; 1.0992x over previous
#include <cuda_runtime.h>
#include <cuda_fp16.h>
#include <cstdint>

// Problem constants
#define S_   1024
#define B_   8
#define D_   1024
#define H_   16
#define HD_  64
#define T_   (B_ * S_)
#define D3_  (3 * D_)

// Scratch
__device__ __half g_qkvh[(size_t)T_ * 3 * D_];
__device__ __half g_attnh[(size_t)T_ * D_];
__device__ float  g_attnout[(size_t)T_ * D_];
__device__ float  g_linv[B_ * H_ * S_];
__device__ __half g_xh[(size_t)T_ * D_];
__device__ __half g_wih[(size_t)D3_ * D_];
__device__ __half g_woh[(size_t)D_ * D_];

__device__ __forceinline__ unsigned su32(const void* p) {
    return (unsigned)__cvta_generic_to_shared(p);
}
__device__ __forceinline__ void cpa16(unsigned dst, const void* src) {
    asm volatile("cp.async.cg.shared.global [%0], [%1], 16;" :: "r"(dst), "l"(src));
}
#define CP_COMMIT() asm volatile("cp.async.commit_group;")
#define CP_WAIT0()  asm volatile("cp.async.wait_group 0;")
#define CP_WAIT1()  asm volatile("cp.async.wait_group 1;")

__device__ __forceinline__ unsigned pkh2(float a, float b) {
    __half2 h = __floats2half2_rn(a, b);
    return *(unsigned*)&h;
}

// fp16 m16n8k16
__device__ __forceinline__ void mma16h(float* d, const unsigned* a, const unsigned* b) {
    asm volatile(
        "mma.sync.aligned.m16n8k16.row.col.f32.f16.f16.f32 "
        "{%0,%1,%2,%3},{%4,%5,%6,%7},{%8,%9},{%0,%1,%2,%3};"
        : "+f"(d[0]), "+f"(d[1]), "+f"(d[2]), "+f"(d[3])
        : "r"(a[0]), "r"(a[1]), "r"(a[2]), "r"(a[3]), "r"(b[0]), "r"(b[1]));
}
__device__ __forceinline__ void ldm4(unsigned* r, unsigned addr) {
    asm volatile("ldmatrix.sync.aligned.m8n8.x4.shared.b16 {%0,%1,%2,%3}, [%4];"
        : "=r"(r[0]), "=r"(r[1]), "=r"(r[2]), "=r"(r[3]) : "r"(addr));
}
__device__ __forceinline__ void ldm4t(unsigned* r, unsigned addr) {
    asm volatile("ldmatrix.sync.aligned.m8n8.x4.trans.shared.b16 {%0,%1,%2,%3}, [%4];"
        : "=r"(r[0]), "=r"(r[1]), "=r"(r[2]), "=r"(r[3]) : "r"(addr));
}

// ---------------------------------------------------------------------------
// fp32 -> fp16 conversion: three segments in one launch
// ---------------------------------------------------------------------------
__global__ void __launch_bounds__(256) to_half3_kernel(
    const float* __restrict__ s0, __half* __restrict__ d0, int n0,
    const float* __restrict__ s1, __half* __restrict__ d1, int n1,
    const float* __restrict__ s2, __half* __restrict__ d2, int n2)
{
    int i = blockIdx.x * blockDim.x + threadIdx.x;
    const float* src;
    __half* dst;
    if (i < n0) { src = s0; dst = d0; }
    else if (i < n0 + n1) { i -= n0; src = s1; dst = d1; }
    else if (i < n0 + n1 + n2) { i -= n0 + n1; src = s2; dst = d2; }
    else return;
    float4 v = ((const float4*)src)[i];
    ((__half2*)dst)[2 * i]     = __floats2half2_rn(v.x, v.y);
    ((__half2*)dst)[2 * i + 1] = __floats2half2_rn(v.z, v.w);
}

// ---------------------------------------------------------------------------
// fp16 GEMM (R11/R13 config — best known): 128x128 tile, 128 threads,
// warp tile 64x64, BK=64 (stride FST=72), 3-stage cp.async, one barrier/iter.
// ---------------------------------------------------------------------------
#define FST 72
#define GSLAB (128 * FST)
template<bool HALF_OUT>
__global__ void __launch_bounds__(128) gemm_hf_kernel(
    const __half* __restrict__ A, const __half* __restrict__ Bm,
    const float* __restrict__ bias, void* __restrict__ Cv,
    int M, int N, int K)
{
    extern __shared__ __half smh[];

    const int tid  = threadIdx.x;
    const int lane = tid & 31;
    const int wid  = tid >> 5;
    const int wm   = wid >> 1;
    const int wn   = wid & 1;
    const int m0 = blockIdx.y * 128;
    const int n0 = blockIdx.x * 128;
    const int gid = lane >> 2;
    const int tig = lane & 3;

    const int aRow = lane & 15;
    const int aCol = (lane >> 4) << 3;
    const int bRow = ((lane >> 4) << 3) + (lane & 7);
    const int bCol = ((lane >> 3) & 1) << 3;

    auto load_slab = [&](int slab, int st) {
        const int k0 = slab * 64;
        const __half* Asrc = A  + (size_t)m0 * K + k0;
        const __half* Bsrc = Bm + (size_t)n0 * K + k0;
        __half* Ab = smh + st * (2 * GSLAB);
        __half* Bb = Ab + GSLAB;
#pragma unroll
        for (int l = 0; l < 8; l++) {
            int lin = tid + l * 128;
            int r = lin >> 3;
            int u = lin & 7;
            cpa16(su32(Ab + r * FST + u * 8), Asrc + (size_t)r * K + u * 8);
            cpa16(su32(Bb + r * FST + u * 8), Bsrc + (size_t)r * K + u * 8);
        }
        CP_COMMIT();
    };

    float acc[4][8][4];
#pragma unroll
    for (int i = 0; i < 4; i++)
#pragma unroll
        for (int j = 0; j < 8; j++)
#pragma unroll
            for (int r = 0; r < 4; r++) acc[i][j][r] = 0.f;

    load_slab(0, 0); load_slab(1, 1);

    const int NIT = K / 64;
    for (int i = 0; i < NIT; i++) {
        const int st = i % 3;
        if (i + 1 < NIT) { CP_WAIT1(); } else { CP_WAIT0(); }
        __syncthreads();
        if (i + 2 < NIT) load_slab(i + 2, (i + 2) % 3);

        const __half* Ac = smh + st * (2 * GSLAB);
        const __half* Bc = Ac + GSLAB;

#pragma unroll
        for (int ks = 0; ks < 4; ks++) {
            unsigned af[4][4], bf[4][4];
#pragma unroll
            for (int mi = 0; mi < 4; mi++)
                ldm4(af[mi], su32(Ac + (wm * 64 + mi * 16 + aRow) * FST + ks * 16 + aCol));
#pragma unroll
            for (int nj = 0; nj < 4; nj++)
                ldm4(bf[nj], su32(Bc + (wn * 64 + nj * 16 + bRow) * FST + ks * 16 + bCol));
#pragma unroll
            for (int mi = 0; mi < 4; mi++)
#pragma unroll
                for (int ni = 0; ni < 8; ni++)
                    mma16h(acc[mi][ni], af[mi], &bf[ni >> 1][(ni & 1) * 2]);
        }
    }

#pragma unroll
    for (int mi = 0; mi < 4; mi++) {
        int m = m0 + wm * 64 + mi * 16 + gid;
#pragma unroll
        for (int ni = 0; ni < 8; ni++) {
            int n = n0 + wn * 64 + ni * 8 + 2 * tig;
            float bx = bias[n], by = bias[n + 1];
            if (HALF_OUT) {
                __half* C = (__half*)Cv;
                *(__half2*)(C + (size_t)m * N + n) =
                    __floats2half2_rn(acc[mi][ni][0] + bx, acc[mi][ni][1] + by);
                *(__half2*)(C + (size_t)(m + 8) * N + n) =
                    __floats2half2_rn(acc[mi][ni][2] + bx, acc[mi][ni][3] + by);
            } else {
                float* C = (float*)Cv;
                *(float2*)(C + (size_t)m * N + n) =
                    make_float2(acc[mi][ni][0] + bx, acc[mi][ni][1] + by);
                *(float2*)(C + (size_t)(m + 8) * N + n) =
                    make_float2(acc[mi][ni][2] + bx, acc[mi][ni][3] + by);
            }
        }
    }
}

// ---------------------------------------------------------------------------
// Flash attention, fp16 MMA. Restructured: exp->PV interleaved per k-slice j
// (pa[4] live for one slice only) + forced 2 CTAs/SM via launch bounds.
// ---------------------------------------------------------------------------
__global__ void __launch_bounds__(256, 2) flash_kernel(const float* __restrict__ td_ptr)
{
    extern __shared__ __half smh[];
    __half* Qs  = smh;
    __half* Ksb = smh + 128 * FST;
    __half* Vsb = Ksb + 2 * 64 * FST;

    const int tid  = threadIdx.x;
    const int lane = tid & 31;
    const int w    = tid >> 5;
    const int gid  = lane >> 2;
    const int tig  = lane & 3;
    const int bh = blockIdx.x;
    const int qt = blockIdx.y;
    const int b  = bh >> 4;
    const int h  = bh & 15;
    const float atd = fabsf(*td_ptr);
    const float scale = 0.125f;

    const int aRow = lane & 15;
    const int aCol = (lane >> 4) << 3;
    const int bRow = ((lane >> 4) << 3) + (lane & 7);
    const int bCol = ((lane >> 3) & 1) << 3;

    {
        const __half* qb = g_qkvh + (size_t)(b * S_ + qt * 128) * D3_ + h * HD_;
#pragma unroll
        for (int l = 0; l < 4; l++) {
            int lin = tid + l * 256;
            int r = lin >> 3;
            int u = lin & 7;
            cpa16(su32(Qs + r * FST + u * 8), qb + (size_t)r * D3_ + u * 8);
        }
    }
    auto issueKV = [&](int kt, int bf) {
        const __half* kb = g_qkvh + (size_t)(b * S_ + kt * 64) * D3_ + D_ + h * HD_;
        const __half* vb = kb + D_;
        __half* Kd = Ksb + bf * 64 * FST;
        __half* Vd = Vsb + bf * 64 * FST;
#pragma unroll
        for (int l = 0; l < 4; l++) {
            int lin = tid + l * 256;
            int r = lin >> 3;
            int u = lin & 7;
            if (r < 64)
                cpa16(su32(Kd + r * FST + u * 8), kb + (size_t)r * D3_ + u * 8);
            else
                cpa16(su32(Vd + (r - 64) * FST + u * 8), vb + (size_t)(r - 64) * D3_ + u * 8);
        }
        CP_COMMIT();
    };

    issueKV(0, 0);
    CP_WAIT0();
    __syncthreads();

    unsigned qf[4][4];
#pragma unroll
    for (int s = 0; s < 4; s++)
        ldm4(qf[s], su32(Qs + (w * 16 + aRow) * FST + s * 16 + aCol));

    float oacc[8][4];
#pragma unroll
    for (int n = 0; n < 8; n++)
#pragma unroll
        for (int r = 0; r < 4; r++) oacc[n][r] = 0.f;
    float ls0 = 0.f, ls1 = 0.f;

    const float qg0f = (float)(qt * 128 + w * 16 + gid);
    const float qg1f = qg0f + 8.f;

    for (int kt = 0; kt < 16; kt++) {
        CP_WAIT0();
        __syncthreads();
        if (kt < 15) issueKV(kt + 1, (kt + 1) & 1);
        const __half* Kc = Ksb + (kt & 1) * 64 * FST;
        const __half* Vc = Vsb + (kt & 1) * 64 * FST;

        // S = Q @ K^T
        float sacc[8][4];
#pragma unroll
        for (int n = 0; n < 8; n++)
#pragma unroll
            for (int r = 0; r < 4; r++) sacc[n][r] = 0.f;
#pragma unroll
        for (int s = 0; s < 4; s++) {
#pragma unroll
            for (int nj = 0; nj < 4; nj++) {
                unsigned kb[4];
                ldm4(kb, su32(Kc + (nj * 16 + bRow) * FST + s * 16 + bCol));
                mma16h(sacc[2 * nj],     qf[s], &kb[0]);
                mma16h(sacc[2 * nj + 1], qf[s], &kb[2]);
            }
        }

        // Per k-slice j: exp (pa[4] live only here) then PV for that slice.
#pragma unroll
        for (int j = 0; j < 4; j++) {
            unsigned pa[4];
            {
                int nb0 = 2 * j, nb1 = 2 * j + 1;
                float c0 = (float)(kt * 64 + nb0 * 8 + 2 * tig);
                float c1 = (float)(kt * 64 + nb1 * 8 + 2 * tig);
                float p00 = __expf(sacc[nb0][0] * scale - atd * fabsf(qg0f - c0));
                float p01 = __expf(sacc[nb0][1] * scale - atd * fabsf(qg0f - c0 - 1.f));
                float p10 = __expf(sacc[nb0][2] * scale - atd * fabsf(qg1f - c0));
                float p11 = __expf(sacc[nb0][3] * scale - atd * fabsf(qg1f - c0 - 1.f));
                float q00 = __expf(sacc[nb1][0] * scale - atd * fabsf(qg0f - c1));
                float q01 = __expf(sacc[nb1][1] * scale - atd * fabsf(qg0f - c1 - 1.f));
                float q10 = __expf(sacc[nb1][2] * scale - atd * fabsf(qg1f - c1));
                float q11 = __expf(sacc[nb1][3] * scale - atd * fabsf(qg1f - c1 - 1.f));
                ls0 += p00 + p01 + q00 + q01;
                ls1 += p10 + p11 + q10 + q11;
                pa[0] = pkh2(p00, p01);
                pa[1] = pkh2(p10, p11);
                pa[2] = pkh2(q00, q01);
                pa[3] = pkh2(q10, q11);
            }
#pragma unroll
            for (int nd = 0; nd < 4; nd++) {
                unsigned vb[4];
                ldm4t(vb, su32(Vc + (j * 16 + aRow) * FST + nd * 16 + aCol));
                mma16h(oacc[2 * nd],     pa, &vb[0]);
                mma16h(oacc[2 * nd + 1], pa, &vb[2]);
            }
        }
    }

#pragma unroll
    for (int o = 1; o <= 2; o <<= 1) {
        ls0 += __shfl_xor_sync(0xffffffffu, ls0, o);
        ls1 += __shfl_xor_sync(0xffffffffu, ls1, o);
    }
    float inv0 = 1.f / ls0, inv1 = 1.f / ls1;
    int t0 = b * S_ + qt * 128 + w * 16 + gid;
#pragma unroll
    for (int nb = 0; nb < 8; nb++) {
        int c = h * HD_ + nb * 8 + 2 * tig;
        *(__half2*)&g_attnh[(size_t)t0 * D_ + c] =
            __floats2half2_rn(oacc[nb][0] * inv0, oacc[nb][1] * inv0);
        *(__half2*)&g_attnh[(size_t)(t0 + 8) * D_ + c] =
            __floats2half2_rn(oacc[nb][2] * inv1, oacc[nb][3] * inv1);
    }
    if (tig == 0) {
        int si = (b * H_ + h) * S_ + qt * 128 + w * 16 + gid;
        g_linv[si] = inv0;
        g_linv[si + 8] = inv1;
    }
}

// ---------------------------------------------------------------------------
// Head-mean weights, fp16 MMA (R13 — known good).
// ---------------------------------------------------------------------------
__global__ void __launch_bounds__(128) weights_kernel(
    const float* __restrict__ td_ptr, float* __restrict__ wout)
{
    extern __shared__ __half smh[];
    __half* Qb = smh;
    __half* Kb = smh + 2 * 64 * FST;
    float*  lsb = (float*)(smh + 4 * 64 * FST);

    const int tid  = threadIdx.x;
    const int lane = tid & 31;
    const int wid  = tid >> 5;
    const int qt = blockIdx.x;
    const int b  = blockIdx.y;
    const int kt = blockIdx.z;
    const float atd = fabsf(*td_ptr);
    const float scale = 0.125f;
    const int gid = lane >> 2;
    const int tig = lane & 3;

    const int aRow = lane & 15;
    const int aCol = (lane >> 4) << 3;
    const int bRow = ((lane >> 4) << 3) + (lane & 7);
    const int bCol = ((lane >> 3) & 1) << 3;

    auto issue = [&](int h, int bf) {
        const __half* qb = g_qkvh + (size_t)(b * S_ + qt * 64) * D3_ + h * HD_;
        const __half* kb = g_qkvh + (size_t)(b * S_ + kt * 64) * D3_ + D_ + h * HD_;
        __half* Qd = Qb + bf * 64 * FST;
        __half* Kd = Kb + bf * 64 * FST;
#pragma unroll
        for (int l = 0; l < 8; l++) {
            int lin = tid + l * 128;
            int r = lin >> 3;
            int u = lin & 7;
            if (r < 64)
                cpa16(su32(Qd + r * FST + u * 8), qb + (size_t)r * D3_ + u * 8);
            else
                cpa16(su32(Kd + (r - 64) * FST + u * 8), kb + (size_t)(r - 64) * D3_ + u * 8);
        }
        CP_COMMIT();
    };

    issue(0, 0);
    {
        int si0 = (b * H_ + 0) * S_ + qt * 64;
        if (tid < 64) lsb[tid] = g_linv[si0 + tid];
    }

    float biasv[4][2][4];
#pragma unroll
    for (int mi = 0; mi < 4; mi++) {
        float qg0 = (float)(qt * 64 + mi * 16 + gid);
        float qg1 = qg0 + 8.f;
#pragma unroll
        for (int ni = 0; ni < 2; ni++) {
            float c0 = (float)(kt * 64 + wid * 16 + ni * 8 + 2 * tig);
            biasv[mi][ni][0] = atd * fabsf(qg0 - c0);
            biasv[mi][ni][1] = atd * fabsf(qg0 - c0 - 1.f);
            biasv[mi][ni][2] = atd * fabsf(qg1 - c0);
            biasv[mi][ni][3] = atd * fabsf(qg1 - c0 - 1.f);
        }
    }

    float wsum[4][2][4];
#pragma unroll
    for (int mi = 0; mi < 4; mi++)
#pragma unroll
        for (int ni = 0; ni < 2; ni++)
#pragma unroll
            for (int r = 0; r < 4; r++) wsum[mi][ni][r] = 0.f;

    for (int h = 0; h < H_; h++) {
        const int bf = h & 1;
        CP_WAIT0();
        __syncthreads();
        if (h < 15) {
            issue(h + 1, bf ^ 1);
            int si0 = (b * H_ + h + 1) * S_ + qt * 64;
            if (tid < 64) lsb[(bf ^ 1) * 64 + tid] = g_linv[si0 + tid];
        }
        const __half* Qc = Qb + bf * 64 * FST;
        const __half* Kc = Kb + bf * 64 * FST;
        const float* ls = lsb + bf * 64;

        float acc[4][2][4];
#pragma unroll
        for (int mi = 0; mi < 4; mi++)
#pragma unroll
            for (int ni = 0; ni < 2; ni++)
#pragma unroll
                for (int r = 0; r < 4; r++) acc[mi][ni][r] = 0.f;

#pragma unroll
        for (int ks = 0; ks < 4; ks++) {
            unsigned bfr[4];
            ldm4(bfr, su32(Kc + (wid * 16 + bRow) * FST + ks * 16 + bCol));
#pragma unroll
            for (int mi = 0; mi < 4; mi++) {
                unsigned af[4];
                ldm4(af, su32(Qc + (mi * 16 + aRow) * FST + ks * 16 + aCol));
                mma16h(acc[mi][0], af, &bfr[0]);
                mma16h(acc[mi][1], af, &bfr[2]);
            }
        }

#pragma unroll
        for (int mi = 0; mi < 4; mi++) {
            float l0v = ls[mi * 16 + gid];
            float l1v = ls[mi * 16 + gid + 8];
#pragma unroll
            for (int ni = 0; ni < 2; ni++) {
                wsum[mi][ni][0] += __expf(fmaf(acc[mi][ni][0], scale, -biasv[mi][ni][0])) * l0v;
                wsum[mi][ni][1] += __expf(fmaf(acc[mi][ni][1], scale, -biasv[mi][ni][1])) * l0v;
                wsum[mi][ni][2] += __expf(fmaf(acc[mi][ni][2], scale, -biasv[mi][ni][2])) * l1v;
                wsum[mi][ni][3] += __expf(fmaf(acc[mi][ni][3], scale, -biasv[mi][ni][3])) * l1v;
            }
        }
    }

    const float inv_h = 1.0f / (float)H_;
#pragma unroll
    for (int mi = 0; mi < 4; mi++) {
        int r0 = qt * 64 + mi * 16 + gid;
#pragma unroll
        for (int ni = 0; ni < 2; ni++) {
            int c = kt * 64 + wid * 16 + ni * 8 + 2 * tig;
            float2 o0 = make_float2(wsum[mi][ni][0] * inv_h, wsum[mi][ni][1] * inv_h);
            float2 o1 = make_float2(wsum[mi][ni][2] * inv_h, wsum[mi][ni][3] * inv_h);
            *(float2*)(wout + (size_t)(b * S_ + r0) * S_ + c) = o0;
            *(float2*)(wout + (size_t)(b * S_ + r0 + 8) * S_ + c) = o1;
        }
    }
}

// ---------------------------------------------------------------------------
// Residual + LayerNorm
// ---------------------------------------------------------------------------
__global__ void __launch_bounds__(256) ln_kernel(
    const float* __restrict__ x, const float* __restrict__ lnw,
    const float* __restrict__ lnb, float* __restrict__ out)
{
    const int row = blockIdx.x;
    const int tid = threadIdx.x;
    const float* xr = x + (size_t)row * D_;
    const float* ar = g_attnout + (size_t)row * D_;

    float4 xv = *(const float4*)(xr + tid * 4);
    float4 av = *(const float4*)(ar + tid * 4);
    float y[4];
    y[0] = xv.x + av.x; y[1] = xv.y + av.y;
    y[2] = xv.z + av.z; y[3] = xv.w + av.w;

    float s  = y[0] + y[1] + y[2] + y[3];
    float sq = y[0]*y[0] + y[1]*y[1] + y[2]*y[2] + y[3]*y[3];
#pragma unroll
    for (int o = 16; o >= 1; o >>= 1) {
        s  += __shfl_xor_sync(0xffffffffu, s,  o);
        sq += __shfl_xor_sync(0xffffffffu, sq, o);
    }
    __shared__ float red[16];
    const int wid = tid >> 5;
    if ((tid & 31) == 0) { red[wid] = s; red[8 + wid] = sq; }
    __syncthreads();
    float st = 0.f, sqt = 0.f;
#pragma unroll
    for (int w = 0; w < 8; w++) { st += red[w]; sqt += red[8 + w]; }
    float mu = st * (1.0f / D_);
    float var = sqt * (1.0f / D_) - mu * mu;
    float rstd = rsqrtf(var + 1e-5f);

    float4 wv = *(const float4*)(lnw + tid * 4);
    float4 bv = *(const float4*)(lnb + tid * 4);
    float4 o4;
    o4.x = (y[0] - mu) * rstd * wv.x + bv.x;
    o4.y = (y[1] - mu) * rstd * wv.y + bv.y;
    o4.z = (y[2] - mu) * rstd * wv.z + bv.z;
    o4.w = (y[3] - mu) * rstd * wv.w + bv.w;
    *(float4*)(out + (size_t)row * D_ + tid * 4) = o4;
}

// ---------------------------------------------------------------------------
extern "C" void kernel_launch(void* const* d_in, const int* in_sizes, int n_in,
                              void* d_out, int out_size)
{
    (void)in_sizes; (void)n_in; (void)out_size;
    const float* x     = (const float*)d_in[0];
    const float* td    = (const float*)d_in[1];
    const float* in_w  = (const float*)d_in[2];
    const float* in_b  = (const float*)d_in[3];
    const float* out_w = (const float*)d_in[4];
    const float* out_b = (const float*)d_in[5];
    const float* lnw   = (const float*)d_in[6];
    const float* lnb   = (const float*)d_in[7];
    float* out  = (float*)d_out;
    float* wout = out + (size_t)T_ * D_;

    float *attnout_p;
    __half *xh_p, *wih_p, *woh_p, *attnh_p, *qkvh_p;
    cudaGetSymbolAddress((void**)&attnout_p, g_attnout);
    cudaGetSymbolAddress((void**)&xh_p, g_xh);
    cudaGetSymbolAddress((void**)&wih_p, g_wih);
    cudaGetSymbolAddress((void**)&woh_p, g_woh);
    cudaGetSymbolAddress((void**)&attnh_p, g_attnh);
    cudaGetSymbolAddress((void**)&qkvh_p, g_qkvh);

    const int gsmem = 3 * 2 * GSLAB * 2;                     // 110592 B
    const int fsmem = (128 * FST + 4 * 64 * FST) * 2;        // 55296 B
    const int wsmem = 4 * 64 * FST * 2 + 2 * 64 * 4;         // 37376 B
    cudaFuncSetAttribute(gemm_hf_kernel<true>,
                         cudaFuncAttributeMaxDynamicSharedMemorySize, gsmem);
    cudaFuncSetAttribute(gemm_hf_kernel<false>,
                         cudaFuncAttributeMaxDynamicSharedMemorySize, gsmem);
    cudaFuncSetAttribute(flash_kernel,
                         cudaFuncAttributeMaxDynamicSharedMemorySize, fsmem);
    cudaFuncSetAttribute(weights_kernel,
                         cudaFuncAttributeMaxDynamicSharedMemorySize, wsmem);

    // 0. Convert GEMM inputs to fp16 (single launch, three segments)
    {
        int n0 = (T_ * D_) / 4;
        int n1 = (D3_ * D_) / 4;
        int n2 = (D_ * D_) / 4;
        int nt = n0 + n1 + n2;
        to_half3_kernel<<<(nt + 255) / 256, 256>>>(
            x, xh_p, n0, in_w, wih_p, n1, out_w, woh_p, n2);
    }

    // 1. QKV projection -> fp16 qkv
    gemm_hf_kernel<true><<<dim3(3 * D_ / 128, T_ / 128), 128, gsmem>>>(
        xh_p, wih_p, in_b, qkvh_p, T_, 3 * D_, D_);

    // 2. Flash attention (fp16 MMA, 2 CTAs/SM) -> g_attnh, g_linv
    flash_kernel<<<dim3(B_ * H_, S_ / 128), 256, fsmem>>>(td);

    // 3. Head-mean weights -> second output
    weights_kernel<<<dim3(S_ / 64, B_, S_ / 64), 128, wsmem>>>(td, wout);

    // 4. Out projection (fp32 output)
    gemm_hf_kernel<false><<<dim3(D_ / 128, T_ / 128), 128, gsmem>>>(
        attnh_p, woh_p, out_b, attnout_p, T_, D_, D_);

    // 5. Residual + LayerNorm
    ln_kernel<<<T_, 256>>>(x, lnw, lnb, out);
}

// round 16
// speedup vs baseline: 1.1169x; 1.0161x over previous
#include <cuda_runtime.h>
#include <cuda_fp16.h>
#include <cstdint>

// Problem constants
#define S_   1024
#define B_   8
#define D_   1024
#define H_   16
#define HD_  64
#define T_   (B_ * S_)
#define D3_  (3 * D_)

// Scratch
__device__ __half g_qkvh[(size_t)T_ * 3 * D_];
__device__ __half g_attnh[(size_t)T_ * D_];
__device__ float  g_attnout[(size_t)T_ * D_];
__device__ float  g_linv[B_ * H_ * S_];
__device__ __half g_xh[(size_t)T_ * D_];
__device__ __half g_wih[(size_t)D3_ * D_];
__device__ __half g_woh[(size_t)D_ * D_];

__device__ __forceinline__ unsigned su32(const void* p) {
    return (unsigned)__cvta_generic_to_shared(p);
}
__device__ __forceinline__ void cpa16(unsigned dst, const void* src) {
    asm volatile("cp.async.cg.shared.global [%0], [%1], 16;" :: "r"(dst), "l"(src));
}
#define CP_COMMIT() asm volatile("cp.async.commit_group;")
#define CP_WAIT0()  asm volatile("cp.async.wait_group 0;")
#define CP_WAIT1()  asm volatile("cp.async.wait_group 1;")

__device__ __forceinline__ unsigned pkh2(float a, float b) {
    __half2 h = __floats2half2_rn(a, b);
    return *(unsigned*)&h;
}

// fp16 m16n8k16
__device__ __forceinline__ void mma16h(float* d, const unsigned* a, const unsigned* b) {
    asm volatile(
        "mma.sync.aligned.m16n8k16.row.col.f32.f16.f16.f32 "
        "{%0,%1,%2,%3},{%4,%5,%6,%7},{%8,%9},{%0,%1,%2,%3};"
        : "+f"(d[0]), "+f"(d[1]), "+f"(d[2]), "+f"(d[3])
        : "r"(a[0]), "r"(a[1]), "r"(a[2]), "r"(a[3]), "r"(b[0]), "r"(b[1]));
}
__device__ __forceinline__ void ldm4(unsigned* r, unsigned addr) {
    asm volatile("ldmatrix.sync.aligned.m8n8.x4.shared.b16 {%0,%1,%2,%3}, [%4];"
        : "=r"(r[0]), "=r"(r[1]), "=r"(r[2]), "=r"(r[3]) : "r"(addr));
}
__device__ __forceinline__ void ldm4t(unsigned* r, unsigned addr) {
    asm volatile("ldmatrix.sync.aligned.m8n8.x4.trans.shared.b16 {%0,%1,%2,%3}, [%4];"
        : "=r"(r[0]), "=r"(r[1]), "=r"(r[2]), "=r"(r[3]) : "r"(addr));
}

#define FST 72
#define GSLAB (128 * FST)

// ---------------------------------------------------------------------------
// fp32 -> fp16 conversion: three segments in one launch
// ---------------------------------------------------------------------------
__global__ void __launch_bounds__(256) to_half3_kernel(
    const float* __restrict__ s0, __half* __restrict__ d0, int n0,
    const float* __restrict__ s1, __half* __restrict__ d1, int n1,
    const float* __restrict__ s2, __half* __restrict__ d2, int n2)
{
    int i = blockIdx.x * blockDim.x + threadIdx.x;
    const float* src;
    __half* dst;
    if (i < n0) { src = s0; dst = d0; }
    else if (i < n0 + n1) { i -= n0; src = s1; dst = d1; }
    else if (i < n0 + n1 + n2) { i -= n0 + n1; src = s2; dst = d2; }
    else return;
    float4 v = ((const float4*)src)[i];
    ((__half2*)dst)[2 * i]     = __floats2half2_rn(v.x, v.y);
    ((__half2*)dst)[2 * i + 1] = __floats2half2_rn(v.z, v.w);
}

// ---------------------------------------------------------------------------
// QKV GEMM (R13 config — best known): 128x128 tile, 128 threads,
// warp tile 64x64, BK=64, 3-stage cp.async, one barrier/iter.
// ---------------------------------------------------------------------------
__global__ void __launch_bounds__(128) gemm_qkv_kernel(
    const __half* __restrict__ A, const __half* __restrict__ Bm,
    const float* __restrict__ bias, __half* __restrict__ C,
    int M, int N, int K)
{
    extern __shared__ __half smh[];

    const int tid  = threadIdx.x;
    const int lane = tid & 31;
    const int wid  = tid >> 5;
    const int wm   = wid >> 1;
    const int wn   = wid & 1;
    const int m0 = blockIdx.y * 128;
    const int n0 = blockIdx.x * 128;
    const int gid = lane >> 2;
    const int tig = lane & 3;

    const int aRow = lane & 15;
    const int aCol = (lane >> 4) << 3;
    const int bRow = ((lane >> 4) << 3) + (lane & 7);
    const int bCol = ((lane >> 3) & 1) << 3;

    auto load_slab = [&](int slab, int st) {
        const int k0 = slab * 64;
        const __half* Asrc = A  + (size_t)m0 * K + k0;
        const __half* Bsrc = Bm + (size_t)n0 * K + k0;
        __half* Ab = smh + st * (2 * GSLAB);
        __half* Bb = Ab + GSLAB;
#pragma unroll
        for (int l = 0; l < 8; l++) {
            int lin = tid + l * 128;
            int r = lin >> 3;
            int u = lin & 7;
            cpa16(su32(Ab + r * FST + u * 8), Asrc + (size_t)r * K + u * 8);
            cpa16(su32(Bb + r * FST + u * 8), Bsrc + (size_t)r * K + u * 8);
        }
        CP_COMMIT();
    };

    float acc[4][8][4];
#pragma unroll
    for (int i = 0; i < 4; i++)
#pragma unroll
        for (int j = 0; j < 8; j++)
#pragma unroll
            for (int r = 0; r < 4; r++) acc[i][j][r] = 0.f;

    load_slab(0, 0); load_slab(1, 1);

    const int NIT = K / 64;
    for (int i = 0; i < NIT; i++) {
        const int st = i % 3;
        if (i + 1 < NIT) { CP_WAIT1(); } else { CP_WAIT0(); }
        __syncthreads();
        if (i + 2 < NIT) load_slab(i + 2, (i + 2) % 3);

        const __half* Ac = smh + st * (2 * GSLAB);
        const __half* Bc = Ac + GSLAB;

#pragma unroll
        for (int ks = 0; ks < 4; ks++) {
            unsigned af[4][4], bf[4][4];
#pragma unroll
            for (int mi = 0; mi < 4; mi++)
                ldm4(af[mi], su32(Ac + (wm * 64 + mi * 16 + aRow) * FST + ks * 16 + aCol));
#pragma unroll
            for (int nj = 0; nj < 4; nj++)
                ldm4(bf[nj], su32(Bc + (wn * 64 + nj * 16 + bRow) * FST + ks * 16 + bCol));
#pragma unroll
            for (int mi = 0; mi < 4; mi++)
#pragma unroll
                for (int ni = 0; ni < 8; ni++)
                    mma16h(acc[mi][ni], af[mi], &bf[ni >> 1][(ni & 1) * 2]);
        }
    }

#pragma unroll
    for (int mi = 0; mi < 4; mi++) {
        int m = m0 + wm * 64 + mi * 16 + gid;
#pragma unroll
        for (int ni = 0; ni < 8; ni++) {
            int n = n0 + wn * 64 + ni * 8 + 2 * tig;
            float bx = bias[n], by = bias[n + 1];
            *(__half2*)(C + (size_t)m * N + n) =
                __floats2half2_rn(acc[mi][ni][0] + bx, acc[mi][ni][1] + by);
            *(__half2*)(C + (size_t)(m + 8) * N + n) =
                __floats2half2_rn(acc[mi][ni][2] + bx, acc[mi][ni][3] + by);
        }
    }
}

// ---------------------------------------------------------------------------
// Out-proj GEMM tile body, "light" config: 128x64 CTA tile, 4 warps (2x2),
// warp tile 64x32, BK=64, 2-stage cp.async. ~128 regs — matches weights
// branch so the fused kernel does not spill.
// ---------------------------------------------------------------------------
#define OPA (128 * FST)               // A slab halves
#define OPB (64 * FST)                // B slab halves
#define OPSTG (OPA + OPB)
__device__ __forceinline__ void outproj_tile_body(
    const float* __restrict__ bias, int m0, int n0)
{
    extern __shared__ __half smh[];

    const int tid  = threadIdx.x;
    const int lane = tid & 31;
    const int wid  = tid >> 5;
    const int wm   = wid >> 1;        // 0..1
    const int wn   = wid & 1;         // 0..1
    const int gid = lane >> 2;
    const int tig = lane & 3;
    const int K = D_;

    const int aRow = lane & 15;
    const int aCol = (lane >> 4) << 3;
    const int bRow = ((lane >> 4) << 3) + (lane & 7);
    const int bCol = ((lane >> 3) & 1) << 3;

    auto load_slab = [&](int slab, int st) {
        const int k0 = slab * 64;
        const __half* Asrc = g_attnh + (size_t)m0 * K + k0;
        const __half* Bsrc = g_woh   + (size_t)n0 * K + k0;
        __half* Ab = smh + st * OPSTG;
        __half* Bb = Ab + OPA;
#pragma unroll
        for (int l = 0; l < 12; l++) {
            int lin = tid + l * 128;     // 0..1535
            int r = lin >> 3;            // 0..191
            int u = lin & 7;
            if (r < 128)
                cpa16(su32(Ab + r * FST + u * 8), Asrc + (size_t)r * K + u * 8);
            else
                cpa16(su32(Bb + (r - 128) * FST + u * 8), Bsrc + (size_t)(r - 128) * K + u * 8);
        }
        CP_COMMIT();
    };

    float acc[4][4][4];
#pragma unroll
    for (int i = 0; i < 4; i++)
#pragma unroll
        for (int j = 0; j < 4; j++)
#pragma unroll
            for (int r = 0; r < 4; r++) acc[i][j][r] = 0.f;

    load_slab(0, 0); load_slab(1, 1);

    const int NIT = K / 64;
    for (int i = 0; i < NIT; i++) {
        const int st = i & 1;
        if (i + 1 < NIT) { CP_WAIT1(); } else { CP_WAIT0(); }
        __syncthreads();
        const __half* Ac = smh + st * OPSTG;
        const __half* Bc = Ac + OPA;

#pragma unroll
        for (int ks = 0; ks < 4; ks++) {
            unsigned af[4][4], bf[2][4];
#pragma unroll
            for (int mi = 0; mi < 4; mi++)
                ldm4(af[mi], su32(Ac + (wm * 64 + mi * 16 + aRow) * FST + ks * 16 + aCol));
#pragma unroll
            for (int nj = 0; nj < 2; nj++)
                ldm4(bf[nj], su32(Bc + (wn * 32 + nj * 16 + bRow) * FST + ks * 16 + bCol));
#pragma unroll
            for (int mi = 0; mi < 4; mi++)
#pragma unroll
                for (int ni = 0; ni < 4; ni++)
                    mma16h(acc[mi][ni], af[mi], &bf[ni >> 1][(ni & 1) * 2]);
        }
        __syncthreads();
        if (i + 2 < NIT) load_slab(i + 2, st);
    }

#pragma unroll
    for (int mi = 0; mi < 4; mi++) {
        int m = m0 + wm * 64 + mi * 16 + gid;
#pragma unroll
        for (int ni = 0; ni < 4; ni++) {
            int n = n0 + wn * 32 + ni * 8 + 2 * tig;
            float bx = bias[n], by = bias[n + 1];
            *(float2*)(g_attnout + (size_t)m * D_ + n) =
                make_float2(acc[mi][ni][0] + bx, acc[mi][ni][1] + by);
            *(float2*)(g_attnout + (size_t)(m + 8) * D_ + n) =
                make_float2(acc[mi][ni][2] + bx, acc[mi][ni][3] + by);
        }
    }
}

// ---------------------------------------------------------------------------
// Weights tile body (R13/R15 config — known good).
// ---------------------------------------------------------------------------
__device__ __forceinline__ void weights_tile_body(
    float atd, float* __restrict__ wout, int qt, int b, int kt)
{
    extern __shared__ __half smh[];
    __half* Qb = smh;
    __half* Kb = smh + 2 * 64 * FST;
    float*  lsb = (float*)(smh + 4 * 64 * FST);

    const int tid  = threadIdx.x;
    const int lane = tid & 31;
    const int wid  = tid >> 5;
    const float scale = 0.125f;
    const int gid = lane >> 2;
    const int tig = lane & 3;

    const int aRow = lane & 15;
    const int aCol = (lane >> 4) << 3;
    const int bRow = ((lane >> 4) << 3) + (lane & 7);
    const int bCol = ((lane >> 3) & 1) << 3;

    auto issue = [&](int h, int bf) {
        const __half* qb = g_qkvh + (size_t)(b * S_ + qt * 64) * D3_ + h * HD_;
        const __half* kb = g_qkvh + (size_t)(b * S_ + kt * 64) * D3_ + D_ + h * HD_;
        __half* Qd = Qb + bf * 64 * FST;
        __half* Kd = Kb + bf * 64 * FST;
#pragma unroll
        for (int l = 0; l < 8; l++) {
            int lin = tid + l * 128;
            int r = lin >> 3;
            int u = lin & 7;
            if (r < 64)
                cpa16(su32(Qd + r * FST + u * 8), qb + (size_t)r * D3_ + u * 8);
            else
                cpa16(su32(Kd + (r - 64) * FST + u * 8), kb + (size_t)(r - 64) * D3_ + u * 8);
        }
        CP_COMMIT();
    };

    issue(0, 0);
    {
        int si0 = (b * H_ + 0) * S_ + qt * 64;
        if (tid < 64) lsb[tid] = g_linv[si0 + tid];
    }

    float biasv[4][2][4];
#pragma unroll
    for (int mi = 0; mi < 4; mi++) {
        float qg0 = (float)(qt * 64 + mi * 16 + gid);
        float qg1 = qg0 + 8.f;
#pragma unroll
        for (int ni = 0; ni < 2; ni++) {
            float c0 = (float)(kt * 64 + wid * 16 + ni * 8 + 2 * tig);
            biasv[mi][ni][0] = atd * fabsf(qg0 - c0);
            biasv[mi][ni][1] = atd * fabsf(qg0 - c0 - 1.f);
            biasv[mi][ni][2] = atd * fabsf(qg1 - c0);
            biasv[mi][ni][3] = atd * fabsf(qg1 - c0 - 1.f);
        }
    }

    float wsum[4][2][4];
#pragma unroll
    for (int mi = 0; mi < 4; mi++)
#pragma unroll
        for (int ni = 0; ni < 2; ni++)
#pragma unroll
            for (int r = 0; r < 4; r++) wsum[mi][ni][r] = 0.f;

    for (int h = 0; h < H_; h++) {
        const int bf = h & 1;
        CP_WAIT0();
        __syncthreads();
        if (h < 15) {
            issue(h + 1, bf ^ 1);
            int si0 = (b * H_ + h + 1) * S_ + qt * 64;
            if (tid < 64) lsb[(bf ^ 1) * 64 + tid] = g_linv[si0 + tid];
        }
        const __half* Qc = Qb + bf * 64 * FST;
        const __half* Kc = Kb + bf * 64 * FST;
        const float* ls = lsb + bf * 64;

        float acc[4][2][4];
#pragma unroll
        for (int mi = 0; mi < 4; mi++)
#pragma unroll
            for (int ni = 0; ni < 2; ni++)
#pragma unroll
                for (int r = 0; r < 4; r++) acc[mi][ni][r] = 0.f;

#pragma unroll
        for (int ks = 0; ks < 4; ks++) {
            unsigned bfr[4];
            ldm4(bfr, su32(Kc + (wid * 16 + bRow) * FST + ks * 16 + bCol));
#pragma unroll
            for (int mi = 0; mi < 4; mi++) {
                unsigned af[4];
                ldm4(af, su32(Qc + (mi * 16 + aRow) * FST + ks * 16 + aCol));
                mma16h(acc[mi][0], af, &bfr[0]);
                mma16h(acc[mi][1], af, &bfr[2]);
            }
        }

#pragma unroll
        for (int mi = 0; mi < 4; mi++) {
            float l0v = ls[mi * 16 + gid];
            float l1v = ls[mi * 16 + gid + 8];
#pragma unroll
            for (int ni = 0; ni < 2; ni++) {
                wsum[mi][ni][0] += __expf(fmaf(acc[mi][ni][0], scale, -biasv[mi][ni][0])) * l0v;
                wsum[mi][ni][1] += __expf(fmaf(acc[mi][ni][1], scale, -biasv[mi][ni][1])) * l0v;
                wsum[mi][ni][2] += __expf(fmaf(acc[mi][ni][2], scale, -biasv[mi][ni][2])) * l1v;
                wsum[mi][ni][3] += __expf(fmaf(acc[mi][ni][3], scale, -biasv[mi][ni][3])) * l1v;
            }
        }
    }

    const float inv_h = 1.0f / (float)H_;
#pragma unroll
    for (int mi = 0; mi < 4; mi++) {
        int r0 = qt * 64 + mi * 16 + gid;
#pragma unroll
        for (int ni = 0; ni < 2; ni++) {
            int c = kt * 64 + wid * 16 + ni * 8 + 2 * tig;
            float2 o0 = make_float2(wsum[mi][ni][0] * inv_h, wsum[mi][ni][1] * inv_h);
            float2 o1 = make_float2(wsum[mi][ni][2] * inv_h, wsum[mi][ni][3] * inv_h);
            *(float2*)(wout + (size_t)(b * S_ + r0) * S_ + c) = o0;
            *(float2*)(wout + (size_t)(b * S_ + r0 + 8) * S_ + c) = o1;
        }
    }
}

// ---------------------------------------------------------------------------
// Fused weights + out-proj. 3072 blocks, interleaved: bx%3==2 -> GEMM (1024),
// else weights (2048). Both branches ~128 regs; 3 CTAs/SM guaranteed.
// ---------------------------------------------------------------------------
__global__ void __launch_bounds__(128, 3) fused_wo_kernel(
    const float* __restrict__ td_ptr, float* __restrict__ wout,
    const float* __restrict__ out_b)
{
    const int bx = blockIdx.x;
    const int r3 = bx % 3;
    if (r3 == 2) {
        int g = bx / 3;                  // 0..1023
        int n0 = (g & 15) * 64;          // D_/64 = 16
        int m0 = (g >> 4) * 128;         // T_/128 = 64
        outproj_tile_body(out_b, m0, n0);
    } else {
        int widx = 2 * (bx / 3) + r3;    // 0..2047
        int qt = widx & 15;
        int b  = (widx >> 4) & 7;
        int kt = widx >> 7;
        weights_tile_body(fabsf(*td_ptr), wout, qt, b, kt);
    }
}

// ---------------------------------------------------------------------------
// Flash attention (R15 — known good): exp->PV interleaved, 2 CTAs/SM.
// ---------------------------------------------------------------------------
__global__ void __launch_bounds__(256, 2) flash_kernel(const float* __restrict__ td_ptr)
{
    extern __shared__ __half smh[];
    __half* Qs  = smh;
    __half* Ksb = smh + 128 * FST;
    __half* Vsb = Ksb + 2 * 64 * FST;

    const int tid  = threadIdx.x;
    const int lane = tid & 31;
    const int w    = tid >> 5;
    const int gid  = lane >> 2;
    const int tig  = lane & 3;
    const int bh = blockIdx.x;
    const int qt = blockIdx.y;
    const int b  = bh >> 4;
    const int h  = bh & 15;
    const float atd = fabsf(*td_ptr);
    const float scale = 0.125f;

    const int aRow = lane & 15;
    const int aCol = (lane >> 4) << 3;
    const int bRow = ((lane >> 4) << 3) + (lane & 7);
    const int bCol = ((lane >> 3) & 1) << 3;

    {
        const __half* qb = g_qkvh + (size_t)(b * S_ + qt * 128) * D3_ + h * HD_;
#pragma unroll
        for (int l = 0; l < 4; l++) {
            int lin = tid + l * 256;
            int r = lin >> 3;
            int u = lin & 7;
            cpa16(su32(Qs + r * FST + u * 8), qb + (size_t)r * D3_ + u * 8);
        }
    }
    auto issueKV = [&](int kt, int bf) {
        const __half* kb = g_qkvh + (size_t)(b * S_ + kt * 64) * D3_ + D_ + h * HD_;
        const __half* vb = kb + D_;
        __half* Kd = Ksb + bf * 64 * FST;
        __half* Vd = Vsb + bf * 64 * FST;
#pragma unroll
        for (int l = 0; l < 4; l++) {
            int lin = tid + l * 256;
            int r = lin >> 3;
            int u = lin & 7;
            if (r < 64)
                cpa16(su32(Kd + r * FST + u * 8), kb + (size_t)r * D3_ + u * 8);
            else
                cpa16(su32(Vd + (r - 64) * FST + u * 8), vb + (size_t)(r - 64) * D3_ + u * 8);
        }
        CP_COMMIT();
    };

    issueKV(0, 0);
    CP_WAIT0();
    __syncthreads();

    unsigned qf[4][4];
#pragma unroll
    for (int s = 0; s < 4; s++)
        ldm4(qf[s], su32(Qs + (w * 16 + aRow) * FST + s * 16 + aCol));

    float oacc[8][4];
#pragma unroll
    for (int n = 0; n < 8; n++)
#pragma unroll
        for (int r = 0; r < 4; r++) oacc[n][r] = 0.f;
    float ls0 = 0.f, ls1 = 0.f;

    const float qg0f = (float)(qt * 128 + w * 16 + gid);
    const float qg1f = qg0f + 8.f;

    for (int kt = 0; kt < 16; kt++) {
        CP_WAIT0();
        __syncthreads();
        if (kt < 15) issueKV(kt + 1, (kt + 1) & 1);
        const __half* Kc = Ksb + (kt & 1) * 64 * FST;
        const __half* Vc = Vsb + (kt & 1) * 64 * FST;

        float sacc[8][4];
#pragma unroll
        for (int n = 0; n < 8; n++)
#pragma unroll
            for (int r = 0; r < 4; r++) sacc[n][r] = 0.f;
#pragma unroll
        for (int s = 0; s < 4; s++) {
#pragma unroll
            for (int nj = 0; nj < 4; nj++) {
                unsigned kb[4];
                ldm4(kb, su32(Kc + (nj * 16 + bRow) * FST + s * 16 + bCol));
                mma16h(sacc[2 * nj],     qf[s], &kb[0]);
                mma16h(sacc[2 * nj + 1], qf[s], &kb[2]);
            }
        }

#pragma unroll
        for (int j = 0; j < 4; j++) {
            unsigned pa[4];
            {
                int nb0 = 2 * j, nb1 = 2 * j + 1;
                float c0 = (float)(kt * 64 + nb0 * 8 + 2 * tig);
                float c1 = (float)(kt * 64 + nb1 * 8 + 2 * tig);
                float p00 = __expf(sacc[nb0][0] * scale - atd * fabsf(qg0f - c0));
                float p01 = __expf(sacc[nb0][1] * scale - atd * fabsf(qg0f - c0 - 1.f));
                float p10 = __expf(sacc[nb0][2] * scale - atd * fabsf(qg1f - c0));
                float p11 = __expf(sacc[nb0][3] * scale - atd * fabsf(qg1f - c0 - 1.f));
                float q00 = __expf(sacc[nb1][0] * scale - atd * fabsf(qg0f - c1));
                float q01 = __expf(sacc[nb1][1] * scale - atd * fabsf(qg0f - c1 - 1.f));
                float q10 = __expf(sacc[nb1][2] * scale - atd * fabsf(qg1f - c1));
                float q11 = __expf(sacc[nb1][3] * scale - atd * fabsf(qg1f - c1 - 1.f));
                ls0 += p00 + p01 + q00 + q01;
                ls1 += p10 + p11 + q10 + q11;
                pa[0] = pkh2(p00, p01);
                pa[1] = pkh2(p10, p11);
                pa[2] = pkh2(q00, q01);
                pa[3] = pkh2(q10, q11);
            }
#pragma unroll
            for (int nd = 0; nd < 4; nd++) {
                unsigned vb[4];
                ldm4t(vb, su32(Vc + (j * 16 + aRow) * FST + nd * 16 + aCol));
                mma16h(oacc[2 * nd],     pa, &vb[0]);
                mma16h(oacc[2 * nd + 1], pa, &vb[2]);
            }
        }
    }

#pragma unroll
    for (int o = 1; o <= 2; o <<= 1) {
        ls0 += __shfl_xor_sync(0xffffffffu, ls0, o);
        ls1 += __shfl_xor_sync(0xffffffffu, ls1, o);
    }
    float inv0 = 1.f / ls0, inv1 = 1.f / ls1;
    int t0 = b * S_ + qt * 128 + w * 16 + gid;
#pragma unroll
    for (int nb = 0; nb < 8; nb++) {
        int c = h * HD_ + nb * 8 + 2 * tig;
        *(__half2*)&g_attnh[(size_t)t0 * D_ + c] =
            __floats2half2_rn(oacc[nb][0] * inv0, oacc[nb][1] * inv0);
        *(__half2*)&g_attnh[(size_t)(t0 + 8) * D_ + c] =
            __floats2half2_rn(oacc[nb][2] * inv1, oacc[nb][3] * inv1);
    }
    if (tig == 0) {
        int si = (b * H_ + h) * S_ + qt * 128 + w * 16 + gid;
        g_linv[si] = inv0;
        g_linv[si + 8] = inv1;
    }
}

// ---------------------------------------------------------------------------
// Residual + LayerNorm
// ---------------------------------------------------------------------------
__global__ void __launch_bounds__(256) ln_kernel(
    const float* __restrict__ x, const float* __restrict__ lnw,
    const float* __restrict__ lnb, float* __restrict__ out)
{
    const int row = blockIdx.x;
    const int tid = threadIdx.x;
    const float* xr = x + (size_t)row * D_;
    const float* ar = g_attnout + (size_t)row * D_;

    float4 xv = *(const float4*)(xr + tid * 4);
    float4 av = *(const float4*)(ar + tid * 4);
    float y[4];
    y[0] = xv.x + av.x; y[1] = xv.y + av.y;
    y[2] = xv.z + av.z; y[3] = xv.w + av.w;

    float s  = y[0] + y[1] + y[2] + y[3];
    float sq = y[0]*y[0] + y[1]*y[1] + y[2]*y[2] + y[3]*y[3];
#pragma unroll
    for (int o = 16; o >= 1; o >>= 1) {
        s  += __shfl_xor_sync(0xffffffffu, s,  o);
        sq += __shfl_xor_sync(0xffffffffu, sq, o);
    }
    __shared__ float red[16];
    const int wid = tid >> 5;
    if ((tid & 31) == 0) { red[wid] = s; red[8 + wid] = sq; }
    __syncthreads();
    float st = 0.f, sqt = 0.f;
#pragma unroll
    for (int w = 0; w < 8; w++) { st += red[w]; sqt += red[8 + w]; }
    float mu = st * (1.0f / D_);
    float var = sqt * (1.0f / D_) - mu * mu;
    float rstd = rsqrtf(var + 1e-5f);

    float4 wv = *(const float4*)(lnw + tid * 4);
    float4 bv = *(const float4*)(lnb + tid * 4);
    float4 o4;
    o4.x = (y[0] - mu) * rstd * wv.x + bv.x;
    o4.y = (y[1] - mu) * rstd * wv.y + bv.y;
    o4.z = (y[2] - mu) * rstd * wv.z + bv.z;
    o4.w = (y[3] - mu) * rstd * wv.w + bv.w;
    *(float4*)(out + (size_t)row * D_ + tid * 4) = o4;
}

// ---------------------------------------------------------------------------
extern "C" void kernel_launch(void* const* d_in, const int* in_sizes, int n_in,
                              void* d_out, int out_size)
{
    (void)in_sizes; (void)n_in; (void)out_size;
    const float* x     = (const float*)d_in[0];
    const float* td    = (const float*)d_in[1];
    const float* in_w  = (const float*)d_in[2];
    const float* in_b  = (const float*)d_in[3];
    const float* out_w = (const float*)d_in[4];
    const float* out_b = (const float*)d_in[5];
    const float* lnw   = (const float*)d_in[6];
    const float* lnb   = (const float*)d_in[7];
    float* out  = (float*)d_out;
    float* wout = out + (size_t)T_ * D_;

    __half *xh_p, *wih_p, *woh_p, *qkvh_p;
    cudaGetSymbolAddress((void**)&xh_p, g_xh);
    cudaGetSymbolAddress((void**)&wih_p, g_wih);
    cudaGetSymbolAddress((void**)&woh_p, g_woh);
    cudaGetSymbolAddress((void**)&qkvh_p, g_qkvh);

    const int gsmem = 3 * 2 * GSLAB * 2;                     // 110592 B
    const int fsmem = (128 * FST + 4 * 64 * FST) * 2;        // 55296 B
    const int wsmem = 2 * OPSTG * 2;                         // 55296 B (>= weights 37376)
    cudaFuncSetAttribute(gemm_qkv_kernel,
                         cudaFuncAttributeMaxDynamicSharedMemorySize, gsmem);
    cudaFuncSetAttribute(fused_wo_kernel,
                         cudaFuncAttributeMaxDynamicSharedMemorySize, wsmem);
    cudaFuncSetAttribute(flash_kernel,
                         cudaFuncAttributeMaxDynamicSharedMemorySize, fsmem);

    // 0. Convert GEMM inputs to fp16 (single launch, three segments)
    {
        int n0 = (T_ * D_) / 4;
        int n1 = (D3_ * D_) / 4;
        int n2 = (D_ * D_) / 4;
        int nt = n0 + n1 + n2;
        to_half3_kernel<<<(nt + 255) / 256, 256>>>(
            x, xh_p, n0, in_w, wih_p, n1, out_w, woh_p, n2);
    }

    // 1. QKV projection -> fp16 qkv
    gemm_qkv_kernel<<<dim3(3 * D_ / 128, T_ / 128), 128, gsmem>>>(
        xh_p, wih_p, in_b, qkvh_p, T_, 3 * D_, D_);

    // 2. Flash attention -> g_attnh, g_linv
    flash_kernel<<<dim3(B_ * H_, S_ / 128), 256, fsmem>>>(td);

    // 3. Fused weights + out-proj (interleaved block types)
    fused_wo_kernel<<<3072, 128, wsmem>>>(td, wout, out_b);

    // 4. Residual + LayerNorm
    ln_kernel<<<T_, 256>>>(x, lnw, lnb, out);
}